// round 6
// baseline (speedup 1.0000x reference)
#include <cuda_runtime.h>
#include <math.h>

#define NN   100000
#define EE   1600000
#define HIDC 64
#define INC  3
#define SCAN_BS   1024
#define SCAN_NB   ((NN + SCAN_BS - 1) / SCAN_BS)   // 98

// ---------------- scratch (static device globals; no allocation) ----------------
__device__ int   g_is64;
__device__ int   g_cnt[NN];
__device__ int   g_rowptr[NN + 1];
__device__ int   g_cursor[NN];
__device__ int   g_srcidx[EE];
__device__ float g_dinv[NN];
__device__ int   g_part[128];
__device__ float g_aggx[NN * INC];
__device__ float g_bufA[NN * HIDC];
__device__ float g_bufB[NN * HIDC];
__device__ float g_probe[NN * 2];      // probe sink, never read

// ---------------- dtype detection for edge_index (int64 vs int32) ----------------
__global__ void k_detect(const void* edges) {
    __shared__ int ok;
    if (threadIdx.x == 0) ok = 1;
    __syncthreads();
    const long long* e64 = (const long long*)edges;
    for (int j = threadIdx.x; j < 1024; j += 256) {
        long long v = e64[j];
        if (v < 0 || v >= NN) ok = 0;
    }
    __syncthreads();
    if (threadIdx.x == 0) g_is64 = ok;
}

__global__ void k_zero_cnt() {
    int i = blockIdx.x * blockDim.x + threadIdx.x;
    if (i < NN) g_cnt[i] = 0;
}

__global__ void k_count(const void* edges) {
    int e = blockIdx.x * blockDim.x + threadIdx.x;
    if (e >= EE) return;
    int d;
    if (g_is64) d = (int)((const long long*)edges)[EE + e];
    else        d = ((const int*)edges)[EE + e];
    atomicAdd(&g_cnt[d], 1);
}

// ---------------- PROBE: synthetic replica of k_agg64's memory behavior --------
// Warp per node, 16 synthetic edges (hash-generated indices), per edge:
// 1 dinv load + 1 float2 feature-row gather. Address stream independent of
// data values, so the profile is representative even over zeroed buffers.
// Output goes to a write-only sink; final kernel output is unaffected.
__global__ void k_probe_agg64(const float* __restrict__ in, float* __restrict__ sink) {
    int gw = (blockIdx.x * blockDim.x + threadIdx.x) >> 5;
    int lane = threadIdx.x & 31;
    if (gw >= NN) return;
    const float2* __restrict__ H = (const float2*)in;
    unsigned u = (unsigned)gw * 2654435761u + 12345u;
    float ax0 = 0.f, ay0 = 0.f, ax1 = 0.f, ay1 = 0.f;
    float ax2 = 0.f, ay2 = 0.f, ax3 = 0.f, ay3 = 0.f;
    #pragma unroll 1
    for (int k = 0; k < 16; k += 4) {
        unsigned u0 = u * 1664525u + 1013904223u;
        unsigned u1 = u0 * 1664525u + 1013904223u;
        unsigned u2 = u1 * 1664525u + 1013904223u;
        unsigned u3 = u2 * 1664525u + 1013904223u;
        u = u3;
        int s0 = (int)(u0 % NN), s1 = (int)(u1 % NN);
        int s2 = (int)(u2 % NN), s3 = (int)(u3 % NN);
        float w0 = g_dinv[s0], w1 = g_dinv[s1], w2 = g_dinv[s2], w3 = g_dinv[s3];
        float2 h0 = H[s0 * 32 + lane];
        float2 h1 = H[s1 * 32 + lane];
        float2 h2 = H[s2 * 32 + lane];
        float2 h3 = H[s3 * 32 + lane];
        ax0 += w0 * h0.x; ay0 += w0 * h0.y;
        ax1 += w1 * h1.x; ay1 += w1 * h1.y;
        ax2 += w2 * h2.x; ay2 += w2 * h2.y;
        ax3 += w3 * h3.x; ay3 += w3 * h3.y;
    }
    if (lane == 0)
        sink[gw * 2] = ((ax0 + ax1) + (ax2 + ax3)) + ((ay0 + ay1) + (ay2 + ay3));
}

// ---------------- two-level exclusive scan of g_cnt -> g_rowptr ----------------
__global__ void k_scan1() {
    __shared__ int sm[SCAN_BS];
    int i = blockIdx.x * SCAN_BS + threadIdx.x;
    int v = (i < NN) ? g_cnt[i] : 0;
    sm[threadIdx.x] = v;
    __syncthreads();
    for (int off = 1; off < SCAN_BS; off <<= 1) {
        int t = 0;
        if (threadIdx.x >= off) t = sm[threadIdx.x - off];
        __syncthreads();
        if (threadIdx.x >= off) sm[threadIdx.x] += t;
        __syncthreads();
    }
    if (i < NN) g_rowptr[i] = sm[threadIdx.x] - v;   // block-local exclusive
    if (threadIdx.x == SCAN_BS - 1) g_part[blockIdx.x] = sm[SCAN_BS - 1];
}

__global__ void k_scan2() {
    __shared__ int sm[128];
    int tid = threadIdx.x;
    int v = (tid < SCAN_NB) ? g_part[tid] : 0;
    sm[tid] = v;
    __syncthreads();
    for (int off = 1; off < 128; off <<= 1) {
        int t = 0;
        if (tid >= off) t = sm[tid - off];
        __syncthreads();
        if (tid >= off) sm[tid] += t;
        __syncthreads();
    }
    if (tid < SCAN_NB) g_part[tid] = sm[tid] - v;    // exclusive block offsets
}

__global__ void k_scan3() {
    int i = blockIdx.x * blockDim.x + threadIdx.x;
    if (i < NN) {
        int r = g_rowptr[i] + g_part[i / SCAN_BS];
        g_rowptr[i] = r;
        g_cursor[i] = r;
        g_dinv[i]   = rsqrtf((float)(g_cnt[i] + 1));   // deg = in-degree + self loop
    }
    if (i == 0) g_rowptr[NN] = EE;
}

__global__ void k_build(const void* edges) {
    int e = blockIdx.x * blockDim.x + threadIdx.x;
    if (e >= EE) return;
    int s, d;
    if (g_is64) {
        s = (int)((const long long*)edges)[e];
        d = (int)((const long long*)edges)[EE + e];
    } else {
        s = ((const int*)edges)[e];
        d = ((const int*)edges)[EE + e];
    }
    int p = atomicAdd(&g_cursor[d], 1);
    g_srcidx[p] = s;
}

// ---------------- aggregation, 3-dim input (layer 1, on raw x) ----------------
__global__ void k_agg3(const float* __restrict__ x) {
    int gw = (blockIdx.x * blockDim.x + threadIdx.x) >> 5;
    int lane = threadIdx.x & 31;
    if (gw >= NN) return;
    int rs = g_rowptr[gw], re = g_rowptr[gw + 1];
    float s0 = 0.f, s1 = 0.f, s2 = 0.f;
    for (int k = rs + lane; k < re; k += 32) {
        int s = g_srcidx[k];
        float w = g_dinv[s];
        s0 += w * x[s * 3 + 0];
        s1 += w * x[s * 3 + 1];
        s2 += w * x[s * 3 + 2];
    }
    #pragma unroll
    for (int o = 16; o > 0; o >>= 1) {
        s0 += __shfl_down_sync(0xffffffffu, s0, o);
        s1 += __shfl_down_sync(0xffffffffu, s1, o);
        s2 += __shfl_down_sync(0xffffffffu, s2, o);
    }
    if (lane == 0) {
        float dv = g_dinv[gw];
        s0 = dv * (s0 + dv * x[gw * 3 + 0]);
        s1 = dv * (s1 + dv * x[gw * 3 + 1]);
        s2 = dv * (s2 + dv * x[gw * 3 + 2]);
        g_aggx[gw * 3 + 0] = s0;
        g_aggx[gw * 3 + 1] = s1;
        g_aggx[gw * 3 + 2] = s2;
    }
}

// ---------------- layer 1 dense: (N,3) @ (3,64) + b, relu ----------------
__global__ void k_lin1(const float* __restrict__ W1, const float* __restrict__ b1,
                       float* __restrict__ out) {
    __shared__ float Ws[3 * HIDC];
    __shared__ float bs[HIDC];
    int tid = threadIdx.x;
    if (tid < 3 * HIDC) Ws[tid] = W1[tid];
    if (tid < HIDC)     bs[tid] = b1[tid];
    __syncthreads();
    int idx = blockIdx.x * blockDim.x + tid;
    if (idx >= NN * HIDC) return;
    int v = idx >> 6, f = idx & 63;
    float a0 = g_aggx[v * 3 + 0], a1 = g_aggx[v * 3 + 1], a2 = g_aggx[v * 3 + 2];
    float h = bs[f] + a0 * Ws[f] + a1 * Ws[HIDC + f] + a2 * Ws[2 * HIDC + f];
    out[idx] = fmaxf(h, 0.f);
}

// ---------------- aggregation, 64-dim: warp per dst node, float2 per lane -------
__global__ void k_agg64(const float* __restrict__ in, float* __restrict__ out) {
    int gw = (blockIdx.x * blockDim.x + threadIdx.x) >> 5;
    int lane = threadIdx.x & 31;
    if (gw >= NN) return;
    int rs = g_rowptr[gw], re = g_rowptr[gw + 1];
    const float2* __restrict__ H = (const float2*)in;
    float ax0 = 0.f, ay0 = 0.f, ax1 = 0.f, ay1 = 0.f;
    float ax2 = 0.f, ay2 = 0.f, ax3 = 0.f, ay3 = 0.f;
    int k = rs;
    for (; k + 4 <= re; k += 4) {
        int s0 = g_srcidx[k + 0];
        int s1 = g_srcidx[k + 1];
        int s2 = g_srcidx[k + 2];
        int s3 = g_srcidx[k + 3];
        float w0 = g_dinv[s0], w1 = g_dinv[s1], w2 = g_dinv[s2], w3 = g_dinv[s3];
        float2 h0 = H[s0 * 32 + lane];
        float2 h1 = H[s1 * 32 + lane];
        float2 h2 = H[s2 * 32 + lane];
        float2 h3 = H[s3 * 32 + lane];
        ax0 += w0 * h0.x; ay0 += w0 * h0.y;
        ax1 += w1 * h1.x; ay1 += w1 * h1.y;
        ax2 += w2 * h2.x; ay2 += w2 * h2.y;
        ax3 += w3 * h3.x; ay3 += w3 * h3.y;
    }
    for (; k < re; k++) {
        int s = g_srcidx[k];
        float w = g_dinv[s];
        float2 h = H[s * 32 + lane];
        ax0 += w * h.x;
        ay0 += w * h.y;
    }
    float dv = g_dinv[gw];
    float2 hv = H[gw * 32 + lane];
    float2 r;
    r.x = dv * (((ax0 + ax1) + (ax2 + ax3)) + dv * hv.x);
    r.y = dv * (((ay0 + ay1) + (ay2 + ay3)) + dv * hv.y);
    ((float2*)out)[gw * 32 + lane] = r;
}

// ---------------- dense 64x64 + bias + relu, tiled ----------------
__global__ void k_lin64(const float* __restrict__ in, const float* __restrict__ W,
                        const float* __restrict__ b, float* __restrict__ out) {
    __shared__ float Ws[HIDC * HIDC];       // W[k][f]
    __shared__ float Xs[HIDC * 36];         // X[k][node], pad 36, float4-aligned
    __shared__ float bs[HIDC];
    int tx = threadIdx.x, ty = threadIdx.y;
    int tid = ty * 64 + tx;                 // 0..511
    int base = blockIdx.x * 32;

    for (int i = tid; i < HIDC * HIDC; i += 512) Ws[i] = W[i];
    if (tid < HIDC) bs[tid] = b[tid];
    for (int i = tid; i < 32 * HIDC; i += 512) {
        int n = i >> 6, k = i & 63;
        int v = base + n;
        Xs[k * 36 + n] = (v < NN) ? in[v * HIDC + k] : 0.f;
    }
    __syncthreads();

    float acc0 = 0.f, acc1 = 0.f, acc2 = 0.f, acc3 = 0.f;
    int n0 = 4 * ty;
    #pragma unroll
    for (int k = 0; k < HIDC; k++) {
        float wv = Ws[k * 64 + tx];
        float4 xv = *(const float4*)&Xs[k * 36 + n0];
        acc0 += xv.x * wv;
        acc1 += xv.y * wv;
        acc2 += xv.z * wv;
        acc3 += xv.w * wv;
    }
    float bb = bs[tx];
    int v0 = base + n0;
    if (v0 + 0 < NN) out[(v0 + 0) * HIDC + tx] = fmaxf(acc0 + bb, 0.f);
    if (v0 + 1 < NN) out[(v0 + 1) * HIDC + tx] = fmaxf(acc1 + bb, 0.f);
    if (v0 + 2 < NN) out[(v0 + 2) * HIDC + tx] = fmaxf(acc2 + bb, 0.f);
    if (v0 + 3 < NN) out[(v0 + 3) * HIDC + tx] = fmaxf(acc3 + bb, 0.f);
}

// ---------------- head: dot with Wm2 (64,1) + bias, sigmoid ----------------
__global__ void k_out(const float* __restrict__ in, const float* __restrict__ Wm2,
                      const float* __restrict__ bm2, float* __restrict__ out) {
    int gw = (blockIdx.x * blockDim.x + threadIdx.x) >> 5;
    int lane = threadIdx.x & 31;
    if (gw >= NN) return;
    float t = in[gw * HIDC + lane] * Wm2[lane] +
              in[gw * HIDC + lane + 32] * Wm2[lane + 32];
    #pragma unroll
    for (int o = 16; o > 0; o >>= 1)
        t += __shfl_down_sync(0xffffffffu, t, o);
    if (lane == 0) {
        float z = t + bm2[0];
        out[gw] = 1.f / (1.f + expf(-z));
    }
}

// ---------------- launch ----------------
extern "C" void kernel_launch(void* const* d_in, const int* in_sizes, int n_in,
                              void* d_out, int out_size) {
    const float* x    = (const float*)d_in[0];
    const void*  ei   = d_in[1];
    const float* W1   = (const float*)d_in[2];
    const float* b1   = (const float*)d_in[3];
    const float* W2   = (const float*)d_in[4];
    const float* b2   = (const float*)d_in[5];
    const float* W3   = (const float*)d_in[6];
    const float* b3   = (const float*)d_in[7];
    const float* Wm1  = (const float*)d_in[8];
    const float* bm1  = (const float*)d_in[9];
    const float* Wm2  = (const float*)d_in[10];
    const float* bm2  = (const float*)d_in[11];
    float* out = (float*)d_out;

    const int TB = 256;
    int gN  = (NN + TB - 1) / TB;
    int gE  = (EE + TB - 1) / TB;
    int gW  = (NN * 32 + TB - 1) / TB;          // warp-per-node grids
    int gF  = (NN * HIDC + TB - 1) / TB;
    dim3 linB(64, 8);
    int gLin = (NN + 31) / 32;

    // ---- CSR preprocessing + probe ----
    // Capture slot = my launch #3 -> k_probe_agg64 (synthetic agg64 replica).
    k_detect<<<1, 256>>>(ei);                    // 0
    k_zero_cnt<<<gN, TB>>>();                    // 1
    k_count<<<gE, TB>>>(ei);                     // 2
    k_probe_agg64<<<gW, TB>>>(g_bufA, g_probe);  // 3  <-- profiled launch
    k_scan1<<<SCAN_NB, SCAN_BS>>>();             // 4
    k_scan2<<<1, 128>>>();                       // 5
    k_scan3<<<gN, TB>>>();                       // 6
    k_build<<<gE, TB>>>(ei);                     // 7

    // ---- layer 1: aggregate x (3-dim), then 3->64 dense + relu ----
    k_agg3<<<gW, TB>>>(x);
    k_lin1<<<gF, TB>>>(W1, b1, g_bufA);

    // ---- layer 2: aggregate (64-dim), dense + relu ----
    k_agg64<<<gW, TB>>>(g_bufA, g_bufB);
    k_lin64<<<gLin, linB>>>(g_bufB, W2, b2, g_bufA);

    // ---- layer 3 ----
    k_agg64<<<gW, TB>>>(g_bufA, g_bufB);
    k_lin64<<<gLin, linB>>>(g_bufB, W3, b3, g_bufA);

    // ---- MLP head ----
    k_lin64<<<gLin, linB>>>(g_bufA, Wm1, bm1, g_bufB);
    k_out<<<gW, TB>>>(g_bufB, Wm2, bm2, out);
}

// round 7
// speedup vs baseline: 2.1182x; 2.1182x over previous
#include <cuda_runtime.h>
#include <cuda_fp16.h>
#include <math.h>

#define NN   100000
#define EE   1600000
#define HIDC 64
#define INC  3
#define SCAN_BS   1024
#define SCAN_NB   ((NN + SCAN_BS - 1) / SCAN_BS)   // 98

// ---------------- scratch (static device globals; no allocation) ----------------
__device__ int   g_is64;
__device__ int   g_cnt[NN];
__device__ int   g_rowptr[NN + 1];
__device__ int   g_cursor[NN];
__device__ int   g_srcidx[EE];
__device__ float g_dinv[NN];
__device__ int   g_part[128];
__device__ float g_aggx[NN * INC];
__device__ float g_bufA[NN * HIDC];
__device__ float g_bufB[NN * HIDC];
__device__ __half2 g_h16[NN * 32];     // fp16 feature buffer for gathered tensors

// ---------------- dtype detection for edge_index (int64 vs int32) ----------------
__global__ void k_detect(const void* edges) {
    __shared__ int ok;
    if (threadIdx.x == 0) ok = 1;
    __syncthreads();
    const long long* e64 = (const long long*)edges;
    for (int j = threadIdx.x; j < 1024; j += 256) {
        long long v = e64[j];
        if (v < 0 || v >= NN) ok = 0;
    }
    __syncthreads();
    if (threadIdx.x == 0) g_is64 = ok;
}

__global__ void k_zero_cnt() {
    int i = blockIdx.x * blockDim.x + threadIdx.x;
    if (i < NN) g_cnt[i] = 0;
}

__global__ void k_count(const void* edges) {
    int e = blockIdx.x * blockDim.x + threadIdx.x;
    if (e >= EE) return;
    int d;
    if (g_is64) d = (int)((const long long*)edges)[EE + e];
    else        d = ((const int*)edges)[EE + e];
    atomicAdd(&g_cnt[d], 1);
}

// ---------------- two-level exclusive scan of g_cnt -> g_rowptr ----------------
__global__ void k_scan1() {
    __shared__ int sm[SCAN_BS];
    int i = blockIdx.x * SCAN_BS + threadIdx.x;
    int v = (i < NN) ? g_cnt[i] : 0;
    sm[threadIdx.x] = v;
    __syncthreads();
    for (int off = 1; off < SCAN_BS; off <<= 1) {
        int t = 0;
        if (threadIdx.x >= off) t = sm[threadIdx.x - off];
        __syncthreads();
        if (threadIdx.x >= off) sm[threadIdx.x] += t;
        __syncthreads();
    }
    if (i < NN) g_rowptr[i] = sm[threadIdx.x] - v;   // block-local exclusive
    if (threadIdx.x == SCAN_BS - 1) g_part[blockIdx.x] = sm[SCAN_BS - 1];
}

__global__ void k_scan2() {
    __shared__ int sm[128];
    int tid = threadIdx.x;
    int v = (tid < SCAN_NB) ? g_part[tid] : 0;
    sm[tid] = v;
    __syncthreads();
    for (int off = 1; off < 128; off <<= 1) {
        int t = 0;
        if (tid >= off) t = sm[tid - off];
        __syncthreads();
        if (tid >= off) sm[tid] += t;
        __syncthreads();
    }
    if (tid < SCAN_NB) g_part[tid] = sm[tid] - v;    // exclusive block offsets
}

__global__ void k_scan3() {
    int i = blockIdx.x * blockDim.x + threadIdx.x;
    if (i < NN) {
        int r = g_rowptr[i] + g_part[i / SCAN_BS];
        g_rowptr[i] = r;
        g_cursor[i] = r;
        g_dinv[i]   = rsqrtf((float)(g_cnt[i] + 1));   // deg = in-degree + self loop
    }
    if (i == 0) g_rowptr[NN] = EE;
}

__global__ void k_build(const void* edges) {
    int e = blockIdx.x * blockDim.x + threadIdx.x;
    if (e >= EE) return;
    int s, d;
    if (g_is64) {
        s = (int)((const long long*)edges)[e];
        d = (int)((const long long*)edges)[EE + e];
    } else {
        s = ((const int*)edges)[e];
        d = ((const int*)edges)[EE + e];
    }
    int p = atomicAdd(&g_cursor[d], 1);
    g_srcidx[p] = s;
}

// ---------------- aggregation, 3-dim input (layer 1, on raw x) ----------------
__global__ void k_agg3(const float* __restrict__ x) {
    int gw = (blockIdx.x * blockDim.x + threadIdx.x) >> 5;
    int lane = threadIdx.x & 31;
    if (gw >= NN) return;
    int rs = g_rowptr[gw], re = g_rowptr[gw + 1];
    float s0 = 0.f, s1 = 0.f, s2 = 0.f;
    for (int k = rs + lane; k < re; k += 32) {
        int s = g_srcidx[k];
        float w = g_dinv[s];
        s0 += w * x[s * 3 + 0];
        s1 += w * x[s * 3 + 1];
        s2 += w * x[s * 3 + 2];
    }
    #pragma unroll
    for (int o = 16; o > 0; o >>= 1) {
        s0 += __shfl_down_sync(0xffffffffu, s0, o);
        s1 += __shfl_down_sync(0xffffffffu, s1, o);
        s2 += __shfl_down_sync(0xffffffffu, s2, o);
    }
    if (lane == 0) {
        float dv = g_dinv[gw];
        s0 = dv * (s0 + dv * x[gw * 3 + 0]);
        s1 = dv * (s1 + dv * x[gw * 3 + 1]);
        s2 = dv * (s2 + dv * x[gw * 3 + 2]);
        g_aggx[gw * 3 + 0] = s0;
        g_aggx[gw * 3 + 1] = s1;
        g_aggx[gw * 3 + 2] = s2;
    }
}

// ---------------- layer 1 dense: (N,3) @ (3,64) + b, relu -> fp16 h1 ------------
// thread per feature-pair: computes features (2p, 2p+1), packs half2.
__global__ void k_lin1(const float* __restrict__ W1, const float* __restrict__ b1,
                       __half2* __restrict__ out) {
    __shared__ float Ws[3 * HIDC];
    __shared__ float bs[HIDC];
    int tid = threadIdx.x;
    if (tid < 3 * HIDC) Ws[tid] = W1[tid];
    if (tid < HIDC)     bs[tid] = b1[tid];
    __syncthreads();
    int idx = blockIdx.x * blockDim.x + tid;        // 0 .. NN*32-1
    if (idx >= NN * 32) return;
    int v = idx >> 5, p = idx & 31;
    int f0 = 2 * p, f1 = 2 * p + 1;
    float a0 = g_aggx[v * 3 + 0], a1 = g_aggx[v * 3 + 1], a2 = g_aggx[v * 3 + 2];
    float h0 = bs[f0] + a0 * Ws[f0] + a1 * Ws[HIDC + f0] + a2 * Ws[2 * HIDC + f0];
    float h1 = bs[f1] + a0 * Ws[f1] + a1 * Ws[HIDC + f1] + a2 * Ws[2 * HIDC + f1];
    out[idx] = __floats2half2_rn(fmaxf(h0, 0.f), fmaxf(h1, 0.f));
}

// ---------------- aggregation, 64-dim fp16 input: warp per node, half2/lane -----
// Gathers 128B rows (half the fp32 traffic); fp32 accumulation; fp32 output.
__global__ void k_agg64h(const __half2* __restrict__ in, float* __restrict__ out) {
    int gw = (blockIdx.x * blockDim.x + threadIdx.x) >> 5;
    int lane = threadIdx.x & 31;
    if (gw >= NN) return;
    int rs = g_rowptr[gw], re = g_rowptr[gw + 1];
    float ax0 = 0.f, ay0 = 0.f, ax1 = 0.f, ay1 = 0.f;
    float ax2 = 0.f, ay2 = 0.f, ax3 = 0.f, ay3 = 0.f;
    int k = rs;
    for (; k + 4 <= re; k += 4) {
        int s0 = g_srcidx[k + 0];
        int s1 = g_srcidx[k + 1];
        int s2 = g_srcidx[k + 2];
        int s3 = g_srcidx[k + 3];
        float w0 = g_dinv[s0], w1 = g_dinv[s1], w2 = g_dinv[s2], w3 = g_dinv[s3];
        float2 h0 = __half22float2(in[s0 * 32 + lane]);
        float2 h1 = __half22float2(in[s1 * 32 + lane]);
        float2 h2 = __half22float2(in[s2 * 32 + lane]);
        float2 h3 = __half22float2(in[s3 * 32 + lane]);
        ax0 += w0 * h0.x; ay0 += w0 * h0.y;
        ax1 += w1 * h1.x; ay1 += w1 * h1.y;
        ax2 += w2 * h2.x; ay2 += w2 * h2.y;
        ax3 += w3 * h3.x; ay3 += w3 * h3.y;
    }
    for (; k < re; k++) {
        int s = g_srcidx[k];
        float w = g_dinv[s];
        float2 h = __half22float2(in[s * 32 + lane]);
        ax0 += w * h.x;
        ay0 += w * h.y;
    }
    float dv = g_dinv[gw];
    float2 hv = __half22float2(in[gw * 32 + lane]);
    float2 r;
    r.x = dv * (((ax0 + ax1) + (ax2 + ax3)) + dv * hv.x);
    r.y = dv * (((ay0 + ay1) + (ay2 + ay3)) + dv * hv.y);
    ((float2*)out)[gw * 32 + lane] = r;
}

// ---------------- dense 64x64 + bias + relu, tiled; fp32 or fp16 output ----------
template <bool HALF_OUT>
__global__ void k_lin64(const float* __restrict__ in, const float* __restrict__ W,
                        const float* __restrict__ b, void* __restrict__ outv) {
    __shared__ float Ws[HIDC * HIDC];       // W[k][f]
    __shared__ float Xs[HIDC * 36];         // X[k][node], pad 36, float4-aligned
    __shared__ float bs[HIDC];
    int tx = threadIdx.x, ty = threadIdx.y;
    int tid = ty * 64 + tx;                 // 0..511
    int base = blockIdx.x * 32;

    for (int i = tid; i < HIDC * HIDC; i += 512) Ws[i] = W[i];
    if (tid < HIDC) bs[tid] = b[tid];
    for (int i = tid; i < 32 * HIDC; i += 512) {
        int n = i >> 6, k = i & 63;
        int v = base + n;
        Xs[k * 36 + n] = (v < NN) ? in[v * HIDC + k] : 0.f;
    }
    __syncthreads();

    float acc0 = 0.f, acc1 = 0.f, acc2 = 0.f, acc3 = 0.f;
    int n0 = 4 * ty;
    #pragma unroll
    for (int k = 0; k < HIDC; k++) {
        float wv = Ws[k * 64 + tx];
        float4 xv = *(const float4*)&Xs[k * 36 + n0];
        acc0 += xv.x * wv;
        acc1 += xv.y * wv;
        acc2 += xv.z * wv;
        acc3 += xv.w * wv;
    }
    float bb = bs[tx];
    int v0 = base + n0;
    float r0 = fmaxf(acc0 + bb, 0.f);
    float r1 = fmaxf(acc1 + bb, 0.f);
    float r2 = fmaxf(acc2 + bb, 0.f);
    float r3 = fmaxf(acc3 + bb, 0.f);
    if (HALF_OUT) {
        __half* out = (__half*)outv;
        if (v0 + 0 < NN) out[(v0 + 0) * HIDC + tx] = __float2half_rn(r0);
        if (v0 + 1 < NN) out[(v0 + 1) * HIDC + tx] = __float2half_rn(r1);
        if (v0 + 2 < NN) out[(v0 + 2) * HIDC + tx] = __float2half_rn(r2);
        if (v0 + 3 < NN) out[(v0 + 3) * HIDC + tx] = __float2half_rn(r3);
    } else {
        float* out = (float*)outv;
        if (v0 + 0 < NN) out[(v0 + 0) * HIDC + tx] = r0;
        if (v0 + 1 < NN) out[(v0 + 1) * HIDC + tx] = r1;
        if (v0 + 2 < NN) out[(v0 + 2) * HIDC + tx] = r2;
        if (v0 + 3 < NN) out[(v0 + 3) * HIDC + tx] = r3;
    }
}

// ---------------- head: dot with Wm2 (64,1) + bias, sigmoid ----------------
__global__ void k_out(const float* __restrict__ in, const float* __restrict__ Wm2,
                      const float* __restrict__ bm2, float* __restrict__ out) {
    int gw = (blockIdx.x * blockDim.x + threadIdx.x) >> 5;
    int lane = threadIdx.x & 31;
    if (gw >= NN) return;
    float t = in[gw * HIDC + lane] * Wm2[lane] +
              in[gw * HIDC + lane + 32] * Wm2[lane + 32];
    #pragma unroll
    for (int o = 16; o > 0; o >>= 1)
        t += __shfl_down_sync(0xffffffffu, t, o);
    if (lane == 0) {
        float z = t + bm2[0];
        out[gw] = 1.f / (1.f + expf(-z));
    }
}

// ---------------- launch ----------------
extern "C" void kernel_launch(void* const* d_in, const int* in_sizes, int n_in,
                              void* d_out, int out_size) {
    const float* x    = (const float*)d_in[0];
    const void*  ei   = d_in[1];
    const float* W1   = (const float*)d_in[2];
    const float* b1   = (const float*)d_in[3];
    const float* W2   = (const float*)d_in[4];
    const float* b2   = (const float*)d_in[5];
    const float* W3   = (const float*)d_in[6];
    const float* b3   = (const float*)d_in[7];
    const float* Wm1  = (const float*)d_in[8];
    const float* bm1  = (const float*)d_in[9];
    const float* Wm2  = (const float*)d_in[10];
    const float* bm2  = (const float*)d_in[11];
    float* out = (float*)d_out;

    const int TB = 256;
    int gN  = (NN + TB - 1) / TB;
    int gE  = (EE + TB - 1) / TB;
    int gW  = (NN * 32 + TB - 1) / TB;          // warp-per-node grids
    int gH  = (NN * 32 + TB - 1) / TB;          // half2-pair grid (lin1)
    dim3 linB(64, 8);
    int gLin = (NN + 31) / 32;

    // ---- CSR preprocessing ----
    k_detect<<<1, 256>>>(ei);
    k_zero_cnt<<<gN, TB>>>();
    k_count<<<gE, TB>>>(ei);
    k_scan1<<<SCAN_NB, SCAN_BS>>>();
    k_scan2<<<1, 128>>>();
    k_scan3<<<gN, TB>>>();
    k_build<<<gE, TB>>>(ei);

    // ---- layer 1: aggregate x (3-dim), then 3->64 dense + relu -> fp16 h1 ----
    k_agg3<<<gW, TB>>>(x);
    k_lin1<<<gH, TB>>>(W1, b1, g_h16);

    // ---- layer 2: fp16 aggregate (128B rows), dense + relu -> fp16 h2 ----
    k_agg64h<<<gW, TB>>>(g_h16, g_bufA);
    k_lin64<true><<<gLin, linB>>>(g_bufA, W2, b2, (void*)g_h16);

    // ---- layer 3: fp16 aggregate, dense + relu -> fp32 h3 ----
    k_agg64h<<<gW, TB>>>(g_h16, g_bufB);
    k_lin64<false><<<gLin, linB>>>(g_bufB, W3, b3, (void*)g_bufA);

    // ---- MLP head ----
    k_lin64<false><<<gLin, linB>>>(g_bufA, Wm1, bm1, (void*)g_bufB);
    k_out<<<gW, TB>>>(g_bufB, Wm2, bm2, out);
}

// round 8
// speedup vs baseline: 2.1185x; 1.0001x over previous
#include <cuda_runtime.h>
#include <cuda_fp16.h>
#include <math.h>

#define NN   100000
#define EE   1600000
#define HIDC 64
#define INC  3
#define SCAN_BS   1024
#define SCAN_NB   ((NN + SCAN_BS - 1) / SCAN_BS)   // 98

// ---------------- scratch (static device globals; no allocation) ----------------
__device__ int   g_is64;
__device__ int   g_cnt[NN];
__device__ int   g_rowptr[NN + 1];
__device__ int   g_cursor[NN];
__device__ int   g_srcidx[EE];
__device__ float g_dinv[NN];
__device__ int   g_part[128];
__device__ float4 g_xs[NN];            // prescaled input features: dinv[v]*x[v], pad
__device__ float g_aggx[NN * INC];
__device__ float g_bufA[NN * HIDC];
__device__ float g_bufB[NN * HIDC];
__device__ __half2 g_h16[NN * 32];     // prescaled fp16 feature buffer (dinv*h)

// ---------------- dtype detection for edge_index (int64 vs int32) ----------------
__global__ void k_detect(const void* edges) {
    __shared__ int ok;
    if (threadIdx.x == 0) ok = 1;
    __syncthreads();
    const long long* e64 = (const long long*)edges;
    for (int j = threadIdx.x; j < 1024; j += 256) {
        long long v = e64[j];
        if (v < 0 || v >= NN) ok = 0;
    }
    __syncthreads();
    if (threadIdx.x == 0) g_is64 = ok;
}

__global__ void k_zero_cnt() {
    int i = blockIdx.x * blockDim.x + threadIdx.x;
    if (i < NN) g_cnt[i] = 0;
}

__global__ void k_count(const void* edges) {
    int e = blockIdx.x * blockDim.x + threadIdx.x;
    if (e >= EE) return;
    int d;
    if (g_is64) d = (int)((const long long*)edges)[EE + e];
    else        d = ((const int*)edges)[EE + e];
    atomicAdd(&g_cnt[d], 1);
}

// ---------------- two-level exclusive scan of g_cnt -> g_rowptr ----------------
__global__ void k_scan1() {
    __shared__ int sm[SCAN_BS];
    int i = blockIdx.x * SCAN_BS + threadIdx.x;
    int v = (i < NN) ? g_cnt[i] : 0;
    sm[threadIdx.x] = v;
    __syncthreads();
    for (int off = 1; off < SCAN_BS; off <<= 1) {
        int t = 0;
        if (threadIdx.x >= off) t = sm[threadIdx.x - off];
        __syncthreads();
        if (threadIdx.x >= off) sm[threadIdx.x] += t;
        __syncthreads();
    }
    if (i < NN) g_rowptr[i] = sm[threadIdx.x] - v;   // block-local exclusive
    if (threadIdx.x == SCAN_BS - 1) g_part[blockIdx.x] = sm[SCAN_BS - 1];
}

__global__ void k_scan2() {
    __shared__ int sm[128];
    int tid = threadIdx.x;
    int v = (tid < SCAN_NB) ? g_part[tid] : 0;
    sm[tid] = v;
    __syncthreads();
    for (int off = 1; off < 128; off <<= 1) {
        int t = 0;
        if (tid >= off) t = sm[tid - off];
        __syncthreads();
        if (tid >= off) sm[tid] += t;
        __syncthreads();
    }
    if (tid < SCAN_NB) g_part[tid] = sm[tid] - v;    // exclusive block offsets
}

__global__ void k_scan3() {
    int i = blockIdx.x * blockDim.x + threadIdx.x;
    if (i < NN) {
        int r = g_rowptr[i] + g_part[i / SCAN_BS];
        g_rowptr[i] = r;
        g_cursor[i] = r;
        g_dinv[i]   = rsqrtf((float)(g_cnt[i] + 1));   // deg = in-degree + self loop
    }
    if (i == 0) g_rowptr[NN] = EE;
}

// ---------------- prescale raw x by dinv into packed float4 ----------------
__global__ void k_prex(const float* __restrict__ x) {
    int i = blockIdx.x * blockDim.x + threadIdx.x;
    if (i >= NN) return;
    float dv = g_dinv[i];
    g_xs[i] = make_float4(dv * x[i * 3 + 0], dv * x[i * 3 + 1], dv * x[i * 3 + 2], 0.f);
}

__global__ void k_build(const void* edges) {
    int e = blockIdx.x * blockDim.x + threadIdx.x;
    if (e >= EE) return;
    int s, d;
    if (g_is64) {
        s = (int)((const long long*)edges)[e];
        d = (int)((const long long*)edges)[EE + e];
    } else {
        s = ((const int*)edges)[e];
        d = ((const int*)edges)[EE + e];
    }
    int p = atomicAdd(&g_cursor[d], 1);
    g_srcidx[p] = s;
}

// ---------------- aggregation, 3-dim prescaled input (layer 1) ----------------
// agg[v] = dinv[v] * (sum_s xs[s] + xs[v]),  xs = dinv*x
__global__ void k_agg3(void) {
    int gw = (blockIdx.x * blockDim.x + threadIdx.x) >> 5;
    int lane = threadIdx.x & 31;
    if (gw >= NN) return;
    int rs = g_rowptr[gw], re = g_rowptr[gw + 1];
    float s0 = 0.f, s1 = 0.f, s2 = 0.f;
    for (int k = rs + lane; k < re; k += 32) {
        int s = g_srcidx[k];
        float4 xv = g_xs[s];
        s0 += xv.x; s1 += xv.y; s2 += xv.z;
    }
    #pragma unroll
    for (int o = 16; o > 0; o >>= 1) {
        s0 += __shfl_down_sync(0xffffffffu, s0, o);
        s1 += __shfl_down_sync(0xffffffffu, s1, o);
        s2 += __shfl_down_sync(0xffffffffu, s2, o);
    }
    if (lane == 0) {
        float dv = g_dinv[gw];
        float4 xv = g_xs[gw];
        g_aggx[gw * 3 + 0] = dv * (s0 + xv.x);
        g_aggx[gw * 3 + 1] = dv * (s1 + xv.y);
        g_aggx[gw * 3 + 2] = dv * (s2 + xv.z);
    }
}

// ---------------- layer 1 dense: (N,3) @ (3,64) + b, relu -> prescaled fp16 -----
// thread per feature-pair: computes features (2p, 2p+1), packs half2 of dinv*relu.
__global__ void k_lin1(const float* __restrict__ W1, const float* __restrict__ b1,
                       __half2* __restrict__ out) {
    __shared__ float Ws[3 * HIDC];
    __shared__ float bs[HIDC];
    int tid = threadIdx.x;
    if (tid < 3 * HIDC) Ws[tid] = W1[tid];
    if (tid < HIDC)     bs[tid] = b1[tid];
    __syncthreads();
    int idx = blockIdx.x * blockDim.x + tid;        // 0 .. NN*32-1
    if (idx >= NN * 32) return;
    int v = idx >> 5, p = idx & 31;
    int f0 = 2 * p, f1 = 2 * p + 1;
    float dv = g_dinv[v];
    float a0 = g_aggx[v * 3 + 0], a1 = g_aggx[v * 3 + 1], a2 = g_aggx[v * 3 + 2];
    float h0 = bs[f0] + a0 * Ws[f0] + a1 * Ws[HIDC + f0] + a2 * Ws[2 * HIDC + f0];
    float h1 = bs[f1] + a0 * Ws[f1] + a1 * Ws[HIDC + f1] + a2 * Ws[2 * HIDC + f1];
    out[idx] = __floats2half2_rn(dv * fmaxf(h0, 0.f), dv * fmaxf(h1, 0.f));
}

// ---------------- aggregation, 64-dim prescaled fp16: warp/node, half2/lane -----
// Pure row-sum (no per-edge weights); fp32 accumulation; true-valued fp32 output.
__global__ void k_agg64h(const __half2* __restrict__ in, float* __restrict__ out) {
    int gw = (blockIdx.x * blockDim.x + threadIdx.x) >> 5;
    int lane = threadIdx.x & 31;
    if (gw >= NN) return;
    int rs = g_rowptr[gw], re = g_rowptr[gw + 1];
    float ax0 = 0.f, ay0 = 0.f, ax1 = 0.f, ay1 = 0.f;
    float ax2 = 0.f, ay2 = 0.f, ax3 = 0.f, ay3 = 0.f;
    int k = rs;
    for (; k + 4 <= re; k += 4) {
        int s0 = g_srcidx[k + 0];
        int s1 = g_srcidx[k + 1];
        int s2 = g_srcidx[k + 2];
        int s3 = g_srcidx[k + 3];
        float2 h0 = __half22float2(in[s0 * 32 + lane]);
        float2 h1 = __half22float2(in[s1 * 32 + lane]);
        float2 h2 = __half22float2(in[s2 * 32 + lane]);
        float2 h3 = __half22float2(in[s3 * 32 + lane]);
        ax0 += h0.x; ay0 += h0.y;
        ax1 += h1.x; ay1 += h1.y;
        ax2 += h2.x; ay2 += h2.y;
        ax3 += h3.x; ay3 += h3.y;
    }
    for (; k < re; k++) {
        int s = g_srcidx[k];
        float2 h = __half22float2(in[s * 32 + lane]);
        ax0 += h.x;
        ay0 += h.y;
    }
    float dv = g_dinv[gw];
    float2 hv = __half22float2(in[gw * 32 + lane]);   // already prescaled
    float2 r;
    r.x = dv * (((ax0 + ax1) + (ax2 + ax3)) + hv.x);
    r.y = dv * (((ay0 + ay1) + (ay2 + ay3)) + hv.y);
    ((float2*)out)[gw * 32 + lane] = r;
}

// ---------------- dense 64x64 + bias + relu; fp32 or prescaled-fp16 output -------
template <bool HALF_OUT>
__global__ void k_lin64(const float* __restrict__ in, const float* __restrict__ W,
                        const float* __restrict__ b, void* __restrict__ outv) {
    __shared__ float Ws[HIDC * HIDC];       // W[k][f]
    __shared__ float Xs[HIDC * 36];         // X[k][node], pad 36, float4-aligned
    __shared__ float bs[HIDC];
    int tx = threadIdx.x, ty = threadIdx.y;
    int tid = ty * 64 + tx;                 // 0..511
    int base = blockIdx.x * 32;

    for (int i = tid; i < HIDC * HIDC; i += 512) Ws[i] = W[i];
    if (tid < HIDC) bs[tid] = b[tid];
    for (int i = tid; i < 32 * HIDC; i += 512) {
        int n = i >> 6, k = i & 63;
        int v = base + n;
        Xs[k * 36 + n] = (v < NN) ? in[v * HIDC + k] : 0.f;
    }
    __syncthreads();

    float acc0 = 0.f, acc1 = 0.f, acc2 = 0.f, acc3 = 0.f;
    int n0 = 4 * ty;
    #pragma unroll
    for (int k = 0; k < HIDC; k++) {
        float wv = Ws[k * 64 + tx];
        float4 xv = *(const float4*)&Xs[k * 36 + n0];
        acc0 += xv.x * wv;
        acc1 += xv.y * wv;
        acc2 += xv.z * wv;
        acc3 += xv.w * wv;
    }
    float bb = bs[tx];
    int v0 = base + n0;
    float r0 = fmaxf(acc0 + bb, 0.f);
    float r1 = fmaxf(acc1 + bb, 0.f);
    float r2 = fmaxf(acc2 + bb, 0.f);
    float r3 = fmaxf(acc3 + bb, 0.f);
    if (HALF_OUT) {
        __half* out = (__half*)outv;
        if (v0 + 0 < NN) out[(v0 + 0) * HIDC + tx] = __float2half_rn(r0 * g_dinv[v0 + 0]);
        if (v0 + 1 < NN) out[(v0 + 1) * HIDC + tx] = __float2half_rn(r1 * g_dinv[v0 + 1]);
        if (v0 + 2 < NN) out[(v0 + 2) * HIDC + tx] = __float2half_rn(r2 * g_dinv[v0 + 2]);
        if (v0 + 3 < NN) out[(v0 + 3) * HIDC + tx] = __float2half_rn(r3 * g_dinv[v0 + 3]);
    } else {
        float* out = (float*)outv;
        if (v0 + 0 < NN) out[(v0 + 0) * HIDC + tx] = r0;
        if (v0 + 1 < NN) out[(v0 + 1) * HIDC + tx] = r1;
        if (v0 + 2 < NN) out[(v0 + 2) * HIDC + tx] = r2;
        if (v0 + 3 < NN) out[(v0 + 3) * HIDC + tx] = r3;
    }
}

// ---------------- head: dot with Wm2 (64,1) + bias, sigmoid ----------------
__global__ void k_out(const float* __restrict__ in, const float* __restrict__ Wm2,
                      const float* __restrict__ bm2, float* __restrict__ out) {
    int gw = (blockIdx.x * blockDim.x + threadIdx.x) >> 5;
    int lane = threadIdx.x & 31;
    if (gw >= NN) return;
    float t = in[gw * HIDC + lane] * Wm2[lane] +
              in[gw * HIDC + lane + 32] * Wm2[lane + 32];
    #pragma unroll
    for (int o = 16; o > 0; o >>= 1)
        t += __shfl_down_sync(0xffffffffu, t, o);
    if (lane == 0) {
        float z = t + bm2[0];
        out[gw] = 1.f / (1.f + expf(-z));
    }
}

// ---------------- launch ----------------
extern "C" void kernel_launch(void* const* d_in, const int* in_sizes, int n_in,
                              void* d_out, int out_size) {
    const float* x    = (const float*)d_in[0];
    const void*  ei   = d_in[1];
    const float* W1   = (const float*)d_in[2];
    const float* b1   = (const float*)d_in[3];
    const float* W2   = (const float*)d_in[4];
    const float* b2   = (const float*)d_in[5];
    const float* W3   = (const float*)d_in[6];
    const float* b3   = (const float*)d_in[7];
    const float* Wm1  = (const float*)d_in[8];
    const float* bm1  = (const float*)d_in[9];
    const float* Wm2  = (const float*)d_in[10];
    const float* bm2  = (const float*)d_in[11];
    float* out = (float*)d_out;

    const int TB = 256;
    int gN  = (NN + TB - 1) / TB;
    int gE  = (EE + TB - 1) / TB;
    int gW  = (NN * 32 + TB - 1) / TB;          // warp-per-node grids
    int gH  = (NN * 32 + TB - 1) / TB;          // half2-pair grid (lin1)
    dim3 linB(64, 8);
    int gLin = (NN + 31) / 32;

    // ---- CSR preprocessing ----
    k_detect<<<1, 256>>>(ei);
    k_zero_cnt<<<gN, TB>>>();
    k_count<<<gE, TB>>>(ei);
    k_scan1<<<SCAN_NB, SCAN_BS>>>();
    k_scan2<<<1, 128>>>();
    k_scan3<<<gN, TB>>>();
    k_prex<<<gN, TB>>>(x);
    k_build<<<gE, TB>>>(ei);

    // ---- layer 1: aggregate prescaled x, then 3->64 dense + relu -> fp16 ----
    k_agg3<<<gW, TB>>>();
    k_lin1<<<gH, TB>>>(W1, b1, g_h16);

    // ---- layer 2: fp16 row-sum aggregate, dense + relu -> prescaled fp16 ----
    k_agg64h<<<gW, TB>>>(g_h16, g_bufA);
    k_lin64<true><<<gLin, linB>>>(g_bufA, W2, b2, (void*)g_h16);

    // ---- layer 3: fp16 row-sum aggregate, dense + relu -> fp32 ----
    k_agg64h<<<gW, TB>>>(g_h16, g_bufB);
    k_lin64<false><<<gLin, linB>>>(g_bufB, W3, b3, (void*)g_bufA);

    // ---- MLP head ----
    k_lin64<false><<<gLin, linB>>>(g_bufA, Wm1, bm1, (void*)g_bufB);
    k_out<<<gW, TB>>>(g_bufB, Wm2, bm2, out);
}

// round 11
// speedup vs baseline: 3.0889x; 1.4581x over previous
#include <cuda_runtime.h>
#include <cuda_fp16.h>
#include <cuda_fp8.h>
#include <math.h>

#define NN   100000
#define EE   1600000
#define HIDC 64
#define INC  3
#define SCAN_BS   1024
#define SCAN_NB   ((NN + SCAN_BS - 1) / SCAN_BS)   // 98

// ---------------- scratch (static device globals; no allocation) ----------------
__device__ int   g_is64;
__device__ int   g_cnt[NN];
__device__ int   g_rowptr[NN + 1];
__device__ int   g_cursor[NN];
__device__ int   g_srcidx[EE];
__device__ float g_dinv[NN];
__device__ int   g_part[128];
__device__ float4 g_xs[NN];            // prescaled input features: dinv[v]*x[v]
__device__ float g_aggx[NN * INC];
__device__ float g_bufA[NN * HIDC];
__device__ float g_bufB[NN * HIDC];
__device__ unsigned short g_q8[NN * 32];   // fp8x2 (e4m3) prescaled feature rows, 64B/row

// ---------------- fp8 helpers ----------------
__device__ __forceinline__ float2 fp8x2_to_float2(unsigned short v) {
    __half2_raw hr = __nv_cvt_fp8x2_to_halfraw2((__nv_fp8x2_storage_t)v, __NV_E4M3);
    __half2 h2 = hr;
    return __half22float2(h2);
}
__device__ __forceinline__ unsigned short float2_to_fp8x2(float x, float y) {
    return (unsigned short)__nv_cvt_float2_to_fp8x2(make_float2(x, y),
                                                    __NV_SATFINITE, __NV_E4M3);
}

// ---------------- dtype detection for edge_index (int64 vs int32) ----------------
__global__ void k_detect(const void* edges) {
    __shared__ int ok;
    if (threadIdx.x == 0) ok = 1;
    __syncthreads();
    const long long* e64 = (const long long*)edges;
    for (int j = threadIdx.x; j < 1024; j += 256) {
        long long v = e64[j];
        if (v < 0 || v >= NN) ok = 0;
    }
    __syncthreads();
    if (threadIdx.x == 0) g_is64 = ok;
}

__global__ void k_zero_cnt() {
    int i = blockIdx.x * blockDim.x + threadIdx.x;
    if (i < NN) g_cnt[i] = 0;
}

__global__ void k_count(const void* edges) {
    int e = blockIdx.x * blockDim.x + threadIdx.x;
    if (e >= EE) return;
    int d;
    if (g_is64) d = (int)((const long long*)edges)[EE + e];
    else        d = ((const int*)edges)[EE + e];
    atomicAdd(&g_cnt[d], 1);
}

// ---------------- two-level exclusive scan of g_cnt -> g_rowptr ----------------
__global__ void k_scan1() {
    __shared__ int sm[SCAN_BS];
    int i = blockIdx.x * SCAN_BS + threadIdx.x;
    int v = (i < NN) ? g_cnt[i] : 0;
    sm[threadIdx.x] = v;
    __syncthreads();
    for (int off = 1; off < SCAN_BS; off <<= 1) {
        int t = 0;
        if (threadIdx.x >= off) t = sm[threadIdx.x - off];
        __syncthreads();
        if (threadIdx.x >= off) sm[threadIdx.x] += t;
        __syncthreads();
    }
    if (i < NN) g_rowptr[i] = sm[threadIdx.x] - v;   // block-local exclusive
    if (threadIdx.x == SCAN_BS - 1) g_part[blockIdx.x] = sm[SCAN_BS - 1];
}

__global__ void k_scan2() {
    __shared__ int sm[128];
    int tid = threadIdx.x;
    int v = (tid < SCAN_NB) ? g_part[tid] : 0;
    sm[tid] = v;
    __syncthreads();
    for (int off = 1; off < 128; off <<= 1) {
        int t = 0;
        if (tid >= off) t = sm[tid - off];
        __syncthreads();
        if (tid >= off) sm[tid] += t;
        __syncthreads();
    }
    if (tid < SCAN_NB) g_part[tid] = sm[tid] - v;    // exclusive block offsets
}

__global__ void k_scan3() {
    int i = blockIdx.x * blockDim.x + threadIdx.x;
    if (i < NN) {
        int r = g_rowptr[i] + g_part[i / SCAN_BS];
        g_rowptr[i] = r;
        g_cursor[i] = r;
        g_dinv[i]   = rsqrtf((float)(g_cnt[i] + 1));   // deg = in-degree + self loop
    }
    if (i == 0) g_rowptr[NN] = EE;
}

// ---------------- prescale raw x by dinv into packed float4 ----------------
__global__ void k_prex(const float* __restrict__ x) {
    int i = blockIdx.x * blockDim.x + threadIdx.x;
    if (i >= NN) return;
    float dv = g_dinv[i];
    g_xs[i] = make_float4(dv * x[i * 3 + 0], dv * x[i * 3 + 1], dv * x[i * 3 + 2], 0.f);
}

__global__ void k_build(const void* edges) {
    int e = blockIdx.x * blockDim.x + threadIdx.x;
    if (e >= EE) return;
    int s, d;
    if (g_is64) {
        s = (int)((const long long*)edges)[e];
        d = (int)((const long long*)edges)[EE + e];
    } else {
        s = ((const int*)edges)[e];
        d = ((const int*)edges)[EE + e];
    }
    int p = atomicAdd(&g_cursor[d], 1);
    g_srcidx[p] = s;
}

// ---------------- aggregation, 3-dim prescaled input (layer 1) ----------------
// agg[v] = dinv[v] * (sum_s xs[s] + xs[v]),  xs = dinv*x
__global__ void k_agg3(void) {
    int gw = (blockIdx.x * blockDim.x + threadIdx.x) >> 5;
    int lane = threadIdx.x & 31;
    if (gw >= NN) return;
    int rs = g_rowptr[gw], re = g_rowptr[gw + 1];
    float s0 = 0.f, s1 = 0.f, s2 = 0.f;
    for (int k = rs + lane; k < re; k += 32) {
        int s = g_srcidx[k];
        float4 xv = g_xs[s];
        s0 += xv.x; s1 += xv.y; s2 += xv.z;
    }
    #pragma unroll
    for (int o = 16; o > 0; o >>= 1) {
        s0 += __shfl_down_sync(0xffffffffu, s0, o);
        s1 += __shfl_down_sync(0xffffffffu, s1, o);
        s2 += __shfl_down_sync(0xffffffffu, s2, o);
    }
    if (lane == 0) {
        float dv = g_dinv[gw];
        float4 xv = g_xs[gw];
        g_aggx[gw * 3 + 0] = dv * (s0 + xv.x);
        g_aggx[gw * 3 + 1] = dv * (s1 + xv.y);
        g_aggx[gw * 3 + 2] = dv * (s2 + xv.z);
    }
}

// ---------------- layer 1 dense: (N,3) @ (3,64) + b, relu -> prescaled fp8 ------
// thread per feature-pair: computes features (2p, 2p+1), packs fp8x2 of dinv*relu.
__global__ void k_lin1(const float* __restrict__ W1, const float* __restrict__ b1,
                       unsigned short* __restrict__ out) {
    __shared__ float Ws[3 * HIDC];
    __shared__ float bs[HIDC];
    int tid = threadIdx.x;
    if (tid < 3 * HIDC) Ws[tid] = W1[tid];
    if (tid < HIDC)     bs[tid] = b1[tid];
    __syncthreads();
    int idx = blockIdx.x * blockDim.x + tid;        // 0 .. NN*32-1
    if (idx >= NN * 32) return;
    int v = idx >> 5, p = idx & 31;
    int f0 = 2 * p, f1 = 2 * p + 1;
    float dv = g_dinv[v];
    float a0 = g_aggx[v * 3 + 0], a1 = g_aggx[v * 3 + 1], a2 = g_aggx[v * 3 + 2];
    float h0 = bs[f0] + a0 * Ws[f0] + a1 * Ws[HIDC + f0] + a2 * Ws[2 * HIDC + f0];
    float h1 = bs[f1] + a0 * Ws[f1] + a1 * Ws[HIDC + f1] + a2 * Ws[2 * HIDC + f1];
    out[idx] = float2_to_fp8x2(dv * fmaxf(h0, 0.f), dv * fmaxf(h1, 0.f));
}

// ---------------- aggregation, 64-dim prescaled fp8: warp/node, fp8x2/lane ------
// Gathers 64B rows; fp32 accumulation; true-valued fp32 output.
__global__ void k_agg64q(const unsigned short* __restrict__ in, float* __restrict__ out) {
    int gw = (blockIdx.x * blockDim.x + threadIdx.x) >> 5;
    int lane = threadIdx.x & 31;
    if (gw >= NN) return;
    int rs = g_rowptr[gw], re = g_rowptr[gw + 1];
    float ax0 = 0.f, ay0 = 0.f, ax1 = 0.f, ay1 = 0.f;
    float ax2 = 0.f, ay2 = 0.f, ax3 = 0.f, ay3 = 0.f;
    int k = rs;
    for (; k + 4 <= re; k += 4) {
        int s0 = g_srcidx[k + 0];
        int s1 = g_srcidx[k + 1];
        int s2 = g_srcidx[k + 2];
        int s3 = g_srcidx[k + 3];
        float2 h0 = fp8x2_to_float2(in[s0 * 32 + lane]);
        float2 h1 = fp8x2_to_float2(in[s1 * 32 + lane]);
        float2 h2 = fp8x2_to_float2(in[s2 * 32 + lane]);
        float2 h3 = fp8x2_to_float2(in[s3 * 32 + lane]);
        ax0 += h0.x; ay0 += h0.y;
        ax1 += h1.x; ay1 += h1.y;
        ax2 += h2.x; ay2 += h2.y;
        ax3 += h3.x; ay3 += h3.y;
    }
    for (; k < re; k++) {
        int s = g_srcidx[k];
        float2 h = fp8x2_to_float2(in[s * 32 + lane]);
        ax0 += h.x;
        ay0 += h.y;
    }
    float dv = g_dinv[gw];
    float2 hv = fp8x2_to_float2(in[gw * 32 + lane]);  // already prescaled self term
    float2 r;
    r.x = dv * (((ax0 + ax1) + (ax2 + ax3)) + hv.x);
    r.y = dv * (((ay0 + ay1) + (ay2 + ay3)) + hv.y);
    ((float2*)out)[gw * 32 + lane] = r;
}

// ---------------- dense 64x64 + bias + relu; fp32 or prescaled-fp8 output --------
template <bool FP8_OUT>
__global__ void k_lin64(const float* __restrict__ in, const float* __restrict__ W,
                        const float* __restrict__ b, void* __restrict__ outv) {
    __shared__ float Ws[HIDC * HIDC];       // W[k][f]
    __shared__ float Xs[HIDC * 36];         // X[k][node], pad 36, float4-aligned
    __shared__ float bs[HIDC];
    int tx = threadIdx.x, ty = threadIdx.y;
    int tid = ty * 64 + tx;                 // 0..511
    int base = blockIdx.x * 32;

    for (int i = tid; i < HIDC * HIDC; i += 512) Ws[i] = W[i];
    if (tid < HIDC) bs[tid] = b[tid];
    for (int i = tid; i < 32 * HIDC; i += 512) {
        int n = i >> 6, k = i & 63;
        int v = base + n;
        Xs[k * 36 + n] = (v < NN) ? in[v * HIDC + k] : 0.f;
    }
    __syncthreads();

    float acc0 = 0.f, acc1 = 0.f, acc2 = 0.f, acc3 = 0.f;
    int n0 = 4 * ty;
    #pragma unroll
    for (int k = 0; k < HIDC; k++) {
        float wv = Ws[k * 64 + tx];
        float4 xv = *(const float4*)&Xs[k * 36 + n0];
        acc0 += xv.x * wv;
        acc1 += xv.y * wv;
        acc2 += xv.z * wv;
        acc3 += xv.w * wv;
    }
    float bb = bs[tx];
    int v0 = base + n0;
    float r0 = fmaxf(acc0 + bb, 0.f);
    float r1 = fmaxf(acc1 + bb, 0.f);
    float r2 = fmaxf(acc2 + bb, 0.f);
    float r3 = fmaxf(acc3 + bb, 0.f);
    if (FP8_OUT) {
        unsigned char* out = (unsigned char*)outv;
        if (v0 + 0 < NN) out[(v0 + 0) * HIDC + tx] = (unsigned char)
            __nv_cvt_float_to_fp8(r0 * g_dinv[v0 + 0], __NV_SATFINITE, __NV_E4M3);
        if (v0 + 1 < NN) out[(v0 + 1) * HIDC + tx] = (unsigned char)
            __nv_cvt_float_to_fp8(r1 * g_dinv[v0 + 1], __NV_SATFINITE, __NV_E4M3);
        if (v0 + 2 < NN) out[(v0 + 2) * HIDC + tx] = (unsigned char)
            __nv_cvt_float_to_fp8(r2 * g_dinv[v0 + 2], __NV_SATFINITE, __NV_E4M3);
        if (v0 + 3 < NN) out[(v0 + 3) * HIDC + tx] = (unsigned char)
            __nv_cvt_float_to_fp8(r3 * g_dinv[v0 + 3], __NV_SATFINITE, __NV_E4M3);
    } else {
        float* out = (float*)outv;
        if (v0 + 0 < NN) out[(v0 + 0) * HIDC + tx] = r0;
        if (v0 + 1 < NN) out[(v0 + 1) * HIDC + tx] = r1;
        if (v0 + 2 < NN) out[(v0 + 2) * HIDC + tx] = r2;
        if (v0 + 3 < NN) out[(v0 + 3) * HIDC + tx] = r3;
    }
}

// ---------------- head: dot with Wm2 (64,1) + bias, sigmoid ----------------
__global__ void k_out(const float* __restrict__ in, const float* __restrict__ Wm2,
                      const float* __restrict__ bm2, float* __restrict__ out) {
    int gw = (blockIdx.x * blockDim.x + threadIdx.x) >> 5;
    int lane = threadIdx.x & 31;
    if (gw >= NN) return;
    float t = in[gw * HIDC + lane] * Wm2[lane] +
              in[gw * HIDC + lane + 32] * Wm2[lane + 32];
    #pragma unroll
    for (int o = 16; o > 0; o >>= 1)
        t += __shfl_down_sync(0xffffffffu, t, o);
    if (lane == 0) {
        float z = t + bm2[0];
        out[gw] = 1.f / (1.f + expf(-z));
    }
}

// ---------------- launch ----------------
extern "C" void kernel_launch(void* const* d_in, const int* in_sizes, int n_in,
                              void* d_out, int out_size) {
    const float* x    = (const float*)d_in[0];
    const void*  ei   = d_in[1];
    const float* W1   = (const float*)d_in[2];
    const float* b1   = (const float*)d_in[3];
    const float* W2   = (const float*)d_in[4];
    const float* b2   = (const float*)d_in[5];
    const float* W3   = (const float*)d_in[6];
    const float* b3   = (const float*)d_in[7];
    const float* Wm1  = (const float*)d_in[8];
    const float* bm1  = (const float*)d_in[9];
    const float* Wm2  = (const float*)d_in[10];
    const float* bm2  = (const float*)d_in[11];
    float* out = (float*)d_out;

    const int TB = 256;
    int gN  = (NN + TB - 1) / TB;
    int gE  = (EE + TB - 1) / TB;
    int gW  = (NN * 32 + TB - 1) / TB;          // warp-per-node grids
    int gH  = (NN * 32 + TB - 1) / TB;          // fp8x2-pair grid (lin1)
    dim3 linB(64, 8);
    int gLin = (NN + 31) / 32;

    // ---- CSR preprocessing ----
    k_detect<<<1, 256>>>(ei);
    k_zero_cnt<<<gN, TB>>>();
    k_count<<<gE, TB>>>(ei);
    k_scan1<<<SCAN_NB, SCAN_BS>>>();
    k_scan2<<<1, 128>>>();
    k_scan3<<<gN, TB>>>();
    k_prex<<<gN, TB>>>(x);
    k_build<<<gE, TB>>>(ei);

    // ---- layer 1: aggregate prescaled x, then 3->64 dense + relu -> fp8 ----
    k_agg3<<<gW, TB>>>();
    k_lin1<<<gH, TB>>>(W1, b1, g_q8);

    // ---- layer 2: fp8 row-sum aggregate (64B rows), dense + relu -> fp8 ----
    k_agg64q<<<gW, TB>>>(g_q8, g_bufA);
    k_lin64<true><<<gLin, linB>>>(g_bufA, W2, b2, (void*)g_q8);

    // ---- layer 3: fp8 row-sum aggregate, dense + relu -> fp32 ----
    k_agg64q<<<gW, TB>>>(g_q8, g_bufB);
    k_lin64<false><<<gLin, linB>>>(g_bufB, W3, b3, (void*)g_bufA);

    // ---- MLP head ----
    k_lin64<false><<<gLin, linB>>>(g_bufA, Wm1, bm1, (void*)g_bufB);
    k_out<<<gW, TB>>>(g_bufB, Wm2, bm2, out);
}

// round 15
// speedup vs baseline: 3.0996x; 1.0035x over previous
#include <cuda_runtime.h>
#include <cuda_fp16.h>
#include <cuda_fp8.h>
#include <math.h>

#define NN   100000
#define EE   1600000
#define HIDC 64
#define INC  3
#define SCAN_BS   1024
#define SCAN_NB   ((NN + SCAN_BS - 1) / SCAN_BS)   // 98

// ---------------- scratch (static device globals; no allocation) ----------------
__device__ int   g_is64;
__device__ int   g_cnt[NN];
__device__ int   g_rowptr[NN + 1];
__device__ int   g_cursor[NN];
__device__ int   g_srcidx[EE];
__device__ float g_dinv[NN];
__device__ int   g_part[128];
__device__ float4 g_xs[NN];            // prescaled input features: dinv[v]*x[v]
__device__ float g_aggx[NN * INC];
__device__ float g_bufA[NN * HIDC];
__device__ float g_bufB[NN * HIDC];
__device__ __align__(16) unsigned short g_q8[NN * 32];  // fp8 (e4m3) rows, 64B/row

// ---------------- fp8 helpers ----------------
__device__ __forceinline__ float2 fp8x2_to_float2(unsigned short v) {
    __half2_raw hr = __nv_cvt_fp8x2_to_halfraw2((__nv_fp8x2_storage_t)v, __NV_E4M3);
    __half2 h2 = hr;
    return __half22float2(h2);
}
__device__ __forceinline__ unsigned short float2_to_fp8x2(float x, float y) {
    return (unsigned short)__nv_cvt_float2_to_fp8x2(make_float2(x, y),
                                                    __NV_SATFINITE, __NV_E4M3);
}

// ---------------- dtype detection for edge_index (int64 vs int32) ----------------
__global__ void k_detect(const void* edges) {
    __shared__ int ok;
    if (threadIdx.x == 0) ok = 1;
    __syncthreads();
    const long long* e64 = (const long long*)edges;
    for (int j = threadIdx.x; j < 1024; j += 256) {
        long long v = e64[j];
        if (v < 0 || v >= NN) ok = 0;
    }
    __syncthreads();
    if (threadIdx.x == 0) g_is64 = ok;
}

__global__ void k_zero_cnt() {
    int i = blockIdx.x * blockDim.x + threadIdx.x;
    if (i < NN) g_cnt[i] = 0;
}

__global__ void k_count(const void* edges) {
    int e = blockIdx.x * blockDim.x + threadIdx.x;
    if (e >= EE) return;
    int d;
    if (g_is64) d = (int)((const long long*)edges)[EE + e];
    else        d = ((const int*)edges)[EE + e];
    atomicAdd(&g_cnt[d], 1);
}

// ---------------- two-level exclusive scan of g_cnt -> g_rowptr ----------------
__global__ void k_scan1() {
    __shared__ int sm[SCAN_BS];
    int i = blockIdx.x * SCAN_BS + threadIdx.x;
    int v = (i < NN) ? g_cnt[i] : 0;
    sm[threadIdx.x] = v;
    __syncthreads();
    for (int off = 1; off < SCAN_BS; off <<= 1) {
        int t = 0;
        if (threadIdx.x >= off) t = sm[threadIdx.x - off];
        __syncthreads();
        if (threadIdx.x >= off) sm[threadIdx.x] += t;
        __syncthreads();
    }
    if (i < NN) g_rowptr[i] = sm[threadIdx.x] - v;   // block-local exclusive
    if (threadIdx.x == SCAN_BS - 1) g_part[blockIdx.x] = sm[SCAN_BS - 1];
}

__global__ void k_scan2() {
    __shared__ int sm[128];
    int tid = threadIdx.x;
    int v = (tid < SCAN_NB) ? g_part[tid] : 0;
    sm[tid] = v;
    __syncthreads();
    for (int off = 1; off < 128; off <<= 1) {
        int t = 0;
        if (tid >= off) t = sm[tid - off];
        __syncthreads();
        if (tid >= off) sm[tid] += t;
        __syncthreads();
    }
    if (tid < SCAN_NB) g_part[tid] = sm[tid] - v;    // exclusive block offsets
}

__global__ void k_scan3() {
    int i = blockIdx.x * blockDim.x + threadIdx.x;
    if (i < NN) {
        int r = g_rowptr[i] + g_part[i / SCAN_BS];
        g_rowptr[i] = r;
        g_cursor[i] = r;
        g_dinv[i]   = rsqrtf((float)(g_cnt[i] + 1));   // deg = in-degree + self loop
    }
    if (i == 0) g_rowptr[NN] = EE;
}

// ---------------- prescale raw x by dinv into packed float4 ----------------
__global__ void k_prex(const float* __restrict__ x) {
    int i = blockIdx.x * blockDim.x + threadIdx.x;
    if (i >= NN) return;
    float dv = g_dinv[i];
    g_xs[i] = make_float4(dv * x[i * 3 + 0], dv * x[i * 3 + 1], dv * x[i * 3 + 2], 0.f);
}

__global__ void k_build(const void* edges) {
    int e = blockIdx.x * blockDim.x + threadIdx.x;
    if (e >= EE) return;
    int s, d;
    if (g_is64) {
        s = (int)((const long long*)edges)[e];
        d = (int)((const long long*)edges)[EE + e];
    } else {
        s = ((const int*)edges)[e];
        d = ((const int*)edges)[EE + e];
    }
    int p = atomicAdd(&g_cursor[d], 1);
    g_srcidx[p] = s;
}

// ---------------- aggregation, 3-dim prescaled input (layer 1) ----------------
// agg[v] = dinv[v] * (sum_s xs[s] + xs[v]),  xs = dinv*x
__global__ void k_agg3(void) {
    int gw = (blockIdx.x * blockDim.x + threadIdx.x) >> 5;
    int lane = threadIdx.x & 31;
    if (gw >= NN) return;
    int rs = g_rowptr[gw], re = g_rowptr[gw + 1];
    float s0 = 0.f, s1 = 0.f, s2 = 0.f;
    for (int k = rs + lane; k < re; k += 32) {
        int s = g_srcidx[k];
        float4 xv = g_xs[s];
        s0 += xv.x; s1 += xv.y; s2 += xv.z;
    }
    #pragma unroll
    for (int o = 16; o > 0; o >>= 1) {
        s0 += __shfl_down_sync(0xffffffffu, s0, o);
        s1 += __shfl_down_sync(0xffffffffu, s1, o);
        s2 += __shfl_down_sync(0xffffffffu, s2, o);
    }
    if (lane == 0) {
        float dv = g_dinv[gw];
        float4 xv = g_xs[gw];
        g_aggx[gw * 3 + 0] = dv * (s0 + xv.x);
        g_aggx[gw * 3 + 1] = dv * (s1 + xv.y);
        g_aggx[gw * 3 + 2] = dv * (s2 + xv.z);
    }
}

// ---------------- layer 1 dense: (N,3) @ (3,64) + b, relu -> prescaled fp8 ------
__global__ void k_lin1(const float* __restrict__ W1, const float* __restrict__ b1,
                       unsigned short* __restrict__ out) {
    __shared__ float Ws[3 * HIDC];
    __shared__ float bs[HIDC];
    int tid = threadIdx.x;
    if (tid < 3 * HIDC) Ws[tid] = W1[tid];
    if (tid < HIDC)     bs[tid] = b1[tid];
    __syncthreads();
    int idx = blockIdx.x * blockDim.x + tid;        // 0 .. NN*32-1
    if (idx >= NN * 32) return;
    int v = idx >> 5, p = idx & 31;
    int f0 = 2 * p, f1 = 2 * p + 1;
    float dv = g_dinv[v];
    float a0 = g_aggx[v * 3 + 0], a1 = g_aggx[v * 3 + 1], a2 = g_aggx[v * 3 + 2];
    float h0 = bs[f0] + a0 * Ws[f0] + a1 * Ws[HIDC + f0] + a2 * Ws[2 * HIDC + f0];
    float h1 = bs[f1] + a0 * Ws[f1] + a1 * Ws[HIDC + f1] + a2 * Ws[2 * HIDC + f1];
    out[idx] = float2_to_fp8x2(dv * fmaxf(h0, 0.f), dv * fmaxf(h1, 0.f));
}

// ---------------- aggregation, 64-dim prescaled fp8: DUAL-EDGE warps ------------
// Row = 16 uints (64B). Warp = 2 groups of 16 lanes; group h handles edges
// rs+h, rs+h+2, ... Each lane loads one uint (4 fp8 features) per edge, so one
// warp LDG instruction services TWO edges (half the gather instructions of R11).
// Partial sums combine across groups via shfl_down(16). fp32 accumulation.
__global__ void k_agg64q(const unsigned* __restrict__ in, float* __restrict__ out) {
    int gw = (blockIdx.x * blockDim.x + threadIdx.x) >> 5;
    int lane = threadIdx.x & 31;
    if (gw >= NN) return;
    int half = lane >> 4;          // 0 or 1
    int sub  = lane & 15;          // uint index within row
    int rs = g_rowptr[gw], re = g_rowptr[gw + 1];
    float a0 = 0.f, a1 = 0.f, a2 = 0.f, a3 = 0.f;
    float b0 = 0.f, b1 = 0.f, b2 = 0.f, b3 = 0.f;
    int k = rs + half;
    // 2-deep unroll per group: edges k and k+2 (4 edges in flight per warp)
    for (; k + 2 < re; k += 4) {
        int sA = g_srcidx[k];
        int sB = g_srcidx[k + 2];
        unsigned wA = in[sA * 16 + sub];
        unsigned wB = in[sB * 16 + sub];
        float2 loA = fp8x2_to_float2((unsigned short)(wA & 0xffffu));
        float2 hiA = fp8x2_to_float2((unsigned short)(wA >> 16));
        float2 loB = fp8x2_to_float2((unsigned short)(wB & 0xffffu));
        float2 hiB = fp8x2_to_float2((unsigned short)(wB >> 16));
        a0 += loA.x; a1 += loA.y; a2 += hiA.x; a3 += hiA.y;
        b0 += loB.x; b1 += loB.y; b2 += hiB.x; b3 += hiB.y;
    }
    if (k < re) {
        int s = g_srcidx[k];
        unsigned w = in[s * 16 + sub];
        float2 lo = fp8x2_to_float2((unsigned short)(w & 0xffffu));
        float2 hi = fp8x2_to_float2((unsigned short)(w >> 16));
        a0 += lo.x; a1 += lo.y; a2 += hi.x; a3 += hi.y;
    }
    a0 += b0; a1 += b1; a2 += b2; a3 += b3;
    // combine the two 16-lane groups
    a0 += __shfl_down_sync(0xffffffffu, a0, 16);
    a1 += __shfl_down_sync(0xffffffffu, a1, 16);
    a2 += __shfl_down_sync(0xffffffffu, a2, 16);
    a3 += __shfl_down_sync(0xffffffffu, a3, 16);
    if (half == 0) {
        unsigned w = in[gw * 16 + sub];                 // prescaled self term
        float2 lo = fp8x2_to_float2((unsigned short)(w & 0xffffu));
        float2 hi = fp8x2_to_float2((unsigned short)(w >> 16));
        float dv = g_dinv[gw];
        float4 r;
        r.x = dv * (a0 + lo.x);
        r.y = dv * (a1 + lo.y);
        r.z = dv * (a2 + hi.x);
        r.w = dv * (a3 + hi.y);
        ((float4*)out)[gw * 16 + sub] = r;
    }
}

// ---------------- dense 64x64 + bias + relu; fp32 or prescaled-fp8 output --------
template <bool FP8_OUT>
__global__ void k_lin64(const float* __restrict__ in, const float* __restrict__ W,
                        const float* __restrict__ b, void* __restrict__ outv) {
    __shared__ float Ws[HIDC * HIDC];       // W[k][f]
    __shared__ float Xs[HIDC * 36];         // X[k][node], pad 36, float4-aligned
    __shared__ float bs[HIDC];
    int tx = threadIdx.x, ty = threadIdx.y;
    int tid = ty * 64 + tx;                 // 0..511
    int base = blockIdx.x * 32;

    for (int i = tid; i < HIDC * HIDC; i += 512) Ws[i] = W[i];
    if (tid < HIDC) bs[tid] = b[tid];
    for (int i = tid; i < 32 * HIDC; i += 512) {
        int n = i >> 6, k = i & 63;
        int v = base + n;
        Xs[k * 36 + n] = (v < NN) ? in[v * HIDC + k] : 0.f;
    }
    __syncthreads();

    float acc0 = 0.f, acc1 = 0.f, acc2 = 0.f, acc3 = 0.f;
    int n0 = 4 * ty;
    #pragma unroll
    for (int k = 0; k < HIDC; k++) {
        float wv = Ws[k * 64 + tx];
        float4 xv = *(const float4*)&Xs[k * 36 + n0];
        acc0 += xv.x * wv;
        acc1 += xv.y * wv;
        acc2 += xv.z * wv;
        acc3 += xv.w * wv;
    }
    float bb = bs[tx];
    int v0 = base + n0;
    float r0 = fmaxf(acc0 + bb, 0.f);
    float r1 = fmaxf(acc1 + bb, 0.f);
    float r2 = fmaxf(acc2 + bb, 0.f);
    float r3 = fmaxf(acc3 + bb, 0.f);
    if (FP8_OUT) {
        unsigned char* out = (unsigned char*)outv;
        if (v0 + 0 < NN) out[(v0 + 0) * HIDC + tx] = (unsigned char)
            __nv_cvt_float_to_fp8(r0 * g_dinv[v0 + 0], __NV_SATFINITE, __NV_E4M3);
        if (v0 + 1 < NN) out[(v0 + 1) * HIDC + tx] = (unsigned char)
            __nv_cvt_float_to_fp8(r1 * g_dinv[v0 + 1], __NV_SATFINITE, __NV_E4M3);
        if (v0 + 2 < NN) out[(v0 + 2) * HIDC + tx] = (unsigned char)
            __nv_cvt_float_to_fp8(r2 * g_dinv[v0 + 2], __NV_SATFINITE, __NV_E4M3);
        if (v0 + 3 < NN) out[(v0 + 3) * HIDC + tx] = (unsigned char)
            __nv_cvt_float_to_fp8(r3 * g_dinv[v0 + 3], __NV_SATFINITE, __NV_E4M3);
    } else {
        float* out = (float*)outv;
        if (v0 + 0 < NN) out[(v0 + 0) * HIDC + tx] = r0;
        if (v0 + 1 < NN) out[(v0 + 1) * HIDC + tx] = r1;
        if (v0 + 2 < NN) out[(v0 + 2) * HIDC + tx] = r2;
        if (v0 + 3 < NN) out[(v0 + 3) * HIDC + tx] = r3;
    }
}

// ---------------- head: dot with Wm2 (64,1) + bias, sigmoid ----------------
__global__ void k_out(const float* __restrict__ in, const float* __restrict__ Wm2,
                      const float* __restrict__ bm2, float* __restrict__ out) {
    int gw = (blockIdx.x * blockDim.x + threadIdx.x) >> 5;
    int lane = threadIdx.x & 31;
    if (gw >= NN) return;
    float t = in[gw * HIDC + lane] * Wm2[lane] +
              in[gw * HIDC + lane + 32] * Wm2[lane + 32];
    #pragma unroll
    for (int o = 16; o > 0; o >>= 1)
        t += __shfl_down_sync(0xffffffffu, t, o);
    if (lane == 0) {
        float z = t + bm2[0];
        out[gw] = 1.f / (1.f + expf(-z));
    }
}

// ---------------- launch ----------------
extern "C" void kernel_launch(void* const* d_in, const int* in_sizes, int n_in,
                              void* d_out, int out_size) {
    const float* x    = (const float*)d_in[0];
    const void*  ei   = d_in[1];
    const float* W1   = (const float*)d_in[2];
    const float* b1   = (const float*)d_in[3];
    const float* W2   = (const float*)d_in[4];
    const float* b2   = (const float*)d_in[5];
    const float* W3   = (const float*)d_in[6];
    const float* b3   = (const float*)d_in[7];
    const float* Wm1  = (const float*)d_in[8];
    const float* bm1  = (const float*)d_in[9];
    const float* Wm2  = (const float*)d_in[10];
    const float* bm2  = (const float*)d_in[11];
    float* out = (float*)d_out;

    const int TB = 256;
    int gN  = (NN + TB - 1) / TB;
    int gE  = (EE + TB - 1) / TB;
    int gW  = (NN * 32 + TB - 1) / TB;          // warp-per-node grids
    int gH  = (NN * 32 + TB - 1) / TB;          // fp8x2-pair grid (lin1)
    dim3 linB(64, 8);
    int gLin = (NN + 31) / 32;

    // ---- CSR preprocessing ----
    k_detect<<<1, 256>>>(ei);
    k_zero_cnt<<<gN, TB>>>();
    k_count<<<gE, TB>>>(ei);
    k_scan1<<<SCAN_NB, SCAN_BS>>>();
    k_scan2<<<1, 128>>>();
    k_scan3<<<gN, TB>>>();
    k_prex<<<gN, TB>>>(x);
    k_build<<<gE, TB>>>(ei);

    // ---- layer 1: aggregate prescaled x, then 3->64 dense + relu -> fp8 ----
    k_agg3<<<gW, TB>>>();
    k_lin1<<<gH, TB>>>(W1, b1, g_q8);

    // ---- layer 2: fp8 dual-edge aggregate (64B rows), dense + relu -> fp8 ----
    k_agg64q<<<gW, TB>>>((const unsigned*)g_q8, g_bufA);
    k_lin64<true><<<gLin, linB>>>(g_bufA, W2, b2, (void*)g_q8);

    // ---- layer 3: fp8 dual-edge aggregate, dense + relu -> fp32 ----
    k_agg64q<<<gW, TB>>>((const unsigned*)g_q8, g_bufB);
    k_lin64<false><<<gLin, linB>>>(g_bufB, W3, b3, (void*)g_bufA);

    // ---- MLP head ----
    k_lin64<false><<<gLin, linB>>>(g_bufA, Wm1, bm1, (void*)g_bufB);
    k_out<<<gW, TB>>>(g_bufB, Wm2, bm2, out);
}